// round 1
// baseline (speedup 1.0000x reference)
#include <cuda_runtime.h>
#include <math.h>

#define FULL 0xffffffffu

static constexpr int B  = 64;
static constexpr int T  = 512;
static constexpr int D  = 768;
static constexpr int LA = 2;   // CRF1 labels
static constexpr int LB = 9;   // CRF2 labels

// ---------------- device scratch (no allocations allowed) ----------------
__device__ float g_logits1[B * T * LA];
__device__ float g_logits2[B * T * LB];
__device__ float g_W1T[LA * D];
__device__ float g_W2T[LB * D];
__device__ float g_ll1[B];
__device__ float g_ll2[B];
__device__ float g_c1[B];
__device__ float g_c2[B];
__device__ float g_cc[B];

// ---------------- prep: transpose W for coalesced/conflict-free reads ----
__global__ void prep_kernel(const float* __restrict__ W1, const float* __restrict__ W2) {
    int i = blockIdx.x * blockDim.x + threadIdx.x;
    if (i < D) {
        g_W1T[i]     = W1[i * LA + 0];
        g_W1T[D + i] = W1[i * LA + 1];
#pragma unroll
        for (int l = 0; l < LB; l++) g_W2T[l * D + i] = W2[i * LB + l];
    }
}

// ---------------- fused projection: logits1 = xW1+b1, logits2 = xW2+b2 ---
// one warp computes 4 rows; lane handles d = k*32+lane; 44 accumulators.
__global__ __launch_bounds__(256) void gemm_kernel(const float* __restrict__ x,
                                                   const float* __restrict__ b1,
                                                   const float* __restrict__ b2) {
    int warp = blockIdx.x * 8 + (threadIdx.x >> 5);
    int lane = threadIdx.x & 31;
    int row0 = warp * 4;
    if (row0 >= B * T) return;

    float acc[4][11];
#pragma unroll
    for (int r = 0; r < 4; r++)
#pragma unroll
        for (int l = 0; l < 11; l++) acc[r][l] = 0.0f;

    const float* xb = x + (size_t)row0 * D + lane;

#pragma unroll 4
    for (int k = 0; k < 24; k++) {
        int d = k * 32 + lane;
        float w[11];
        w[0] = g_W1T[d];
        w[1] = g_W1T[D + d];
#pragma unroll
        for (int l = 0; l < 9; l++) w[2 + l] = g_W2T[l * D + d];
        float xv[4];
#pragma unroll
        for (int r = 0; r < 4; r++) xv[r] = xb[(size_t)r * D + k * 32];
#pragma unroll
        for (int r = 0; r < 4; r++)
#pragma unroll
            for (int l = 0; l < 11; l++) acc[r][l] = fmaf(xv[r], w[l], acc[r][l]);
    }

#pragma unroll
    for (int r = 0; r < 4; r++)
#pragma unroll
        for (int l = 0; l < 11; l++) {
            float v = acc[r][l];
#pragma unroll
            for (int o = 16; o; o >>= 1) v += __shfl_xor_sync(FULL, v, o);
            acc[r][l] = v;
        }

    if (lane == 0) {
#pragma unroll
        for (int r = 0; r < 4; r++) {
            int row = row0 + r;
            g_logits1[row * LA + 0] = acc[r][0] + b1[0];
            g_logits1[row * LA + 1] = acc[r][1] + b1[1];
#pragma unroll
            for (int l = 0; l < 9; l++) g_logits2[row * LB + l] = acc[r][2 + l] + b2[l];
        }
    }
}

// ---------------- CRF log-partition scan (one warp, lane j = label j) ----
// Base-2 domain. d_j = log2-alpha_j - Z (lazily renormalized every 8 steps).
// new_j = log2( sum_i 2^{d_i} * E_ij ) + logit_j*log2e, E_ij = e^{t_ij}.
// Only ONE warp-wide EX2 per step (instead of L).
template <int L>
__device__ __forceinline__ float crf_lognorm(const float* __restrict__ lgs,  // shared [T][L]
                                             const float* __restrict__ trans,
                                             int sl) {
    const int j = threadIdx.x & 31;
    const float K = 1.4426950408889634f;  // log2(e)

    float E[L];
#pragma unroll
    for (int i = 0; i < L; i++) E[i] = (j < L) ? __expf(trans[i * L + j]) : 0.0f;

    float d = (j < L) ? lgs[j] * K : -1.0e30f;
    float Z = 0.0f;

    for (int t = 1; t < sl; ++t) {
        float lv = (j < L) ? lgs[t * L + j] : 0.0f;  // LDS, issues early (off critical path)
        float e = exp2f(d);                           // single MUFU.EX2
        float p[L];
#pragma unroll
        for (int i = 0; i < L; i++) p[i] = __shfl_sync(FULL, e, i) * E[i];
#pragma unroll
        for (int st = 1; st < L; st <<= 1)
#pragma unroll
            for (int i = 0; i + st < L; i += st * 2) p[i] += p[i + st];
        d = __log2f(p[0]) + lv * K;
        if ((t & 7) == 0) {                           // lazy renormalization
            float r = __shfl_sync(FULL, d, 0);
            d -= r;
            Z += r;
        }
    }

    // final logsumexp over lanes < L (exact max this time)
    float dv = (j < L) ? d : -3.0e38f;
    float m = dv;
#pragma unroll
    for (int o = 16; o; o >>= 1) m = fmaxf(m, __shfl_xor_sync(FULL, m, o));
    float ev = (j < L) ? exp2f(dv - m) : 0.0f;
#pragma unroll
    for (int o = 16; o; o >>= 1) ev += __shfl_xor_sync(FULL, ev, o);
    return (Z + m + __log2f(ev)) * 0.6931471805599453f;  // back to natural log
}

// ---------------- Viterbi decode (one warp) ------------------------------
// Forward max-plus with backpointers in shared; backward pointer-chase.
// max is exact in FP -> bit-identical to reference given identical logits.
template <int L>
__device__ __forceinline__ void crf_decode_warp(const float* __restrict__ lgs,  // shared [T][L]
                                                const float* __restrict__ trans,
                                                int sl,
                                                unsigned char* __restrict__ bp_sh,   // [T][L]
                                                unsigned char* __restrict__ vit_sh)  // [T]
{
    const int j = threadIdx.x & 31;
    float Trow[L];
#pragma unroll
    for (int i = 0; i < L; i++) Trow[i] = (j < L) ? trans[i * L + j] : 0.0f;

    float v = (j < L) ? lgs[j] : -3.0e38f;

    for (int t = 1; t < sl; ++t) {
        float lv = (j < L) ? lgs[t * L + j] : 0.0f;
        float q[L];
#pragma unroll
        for (int i = 0; i < L; i++) q[i] = __shfl_sync(FULL, v, i) + Trow[i];
        float r[L];
#pragma unroll
        for (int i = 0; i < L; i++) r[i] = q[i];
#pragma unroll
        for (int st = 1; st < L; st <<= 1)
#pragma unroll
            for (int i = 0; i + st < L; i += st * 2) r[i] = fmaxf(r[i], r[i + st]);
        float m = r[0];
        int bp = 0;
#pragma unroll
        for (int i = L - 1; i >= 0; i--) bp = (q[i] == m) ? i : bp;  // first-max index
        if (j < L) bp_sh[t * L + j] = (unsigned char)bp;
        v = m + lv;
    }

    // last = argmax_j v_j (first max, ascending strict >)
    float q[L];
#pragma unroll
    for (int i = 0; i < L; i++) q[i] = __shfl_sync(FULL, v, i);
    float best = q[0];
    int last = 0;
#pragma unroll
    for (int i = 1; i < L; i++)
        if (q[i] > best) { best = q[i]; last = i; }

    // tail: positions >= sl-1 all equal `last` (identity backpointers)
    for (int t = sl - 1 + j; t < T; t += 32) vit_sh[t] = (unsigned char)last;
    __syncwarp();

    if (j == 0) {
        int cur = last;
        for (int t = sl - 1; t >= 1; --t) {
            cur = bp_sh[t * L + cur];
            vit_sh[t - 1] = (unsigned char)cur;
        }
    }
    __syncwarp();
}

// ---------------- scan kernel: 1 block = 1 batch, 4 role warps -----------
__global__ __launch_bounds__(128) void scan_kernel(const int* __restrict__ label,
                                                   const int* __restrict__ seqlen,
                                                   const float* __restrict__ trans1,
                                                   const float* __restrict__ trans2,
                                                   float* __restrict__ out,
                                                   int out_size) {
    __shared__ float lg1s[T * LA];            //  4 KB
    __shared__ float lg2s[T * LB];            // 18 KB
    __shared__ unsigned char bp1[T * LA];     //  1 KB
    __shared__ unsigned char bp2[T * LB];     //  4.5 KB
    __shared__ unsigned char vit1s[T];
    __shared__ unsigned char vit2s[T];
    __shared__ float sred[12];

    int b = blockIdx.x;
    int sl = seqlen[b];
    int wid = threadIdx.x >> 5;
    int lane = threadIdx.x & 31;
    const int* lab = label + b * T;

    // stage logits into shared (coalesced)
    {
        const float* lg1g = g_logits1 + b * T * LA;
        const float* lg2g = g_logits2 + b * T * LB;
        for (int i = threadIdx.x; i < T * LA; i += 128) lg1s[i] = lg1g[i];
        for (int i = threadIdx.x; i < T * LB; i += 128) lg2s[i] = lg2g[i];
    }
    __syncthreads();

    if (wid == 0) {
        // CRF1 gold score + log-partition
        float s = 0.0f;
        for (int t = lane; t < sl; t += 32) {
            int tg = (lab[t] > 0) ? 1 : 0;
            s += lg1s[t * LA + tg];
            if (t > 0) {
                int tp = (lab[t - 1] > 0) ? 1 : 0;
                s += trans1[tp * LA + tg];
            }
        }
#pragma unroll
        for (int o = 16; o; o >>= 1) s += __shfl_xor_sync(FULL, s, o);
        float ln = crf_lognorm<LA>(lg1s, trans1, sl);
        if (lane == 0) g_ll1[b] = s - ln;
    } else if (wid == 1) {
        crf_decode_warp<LA>(lg1s, trans1, sl, bp1, vit1s);
    } else if (wid == 2) {
        float s = 0.0f;
        for (int t = lane; t < sl; t += 32) {
            int tg = lab[t];
            s += lg2s[t * LB + tg];
            if (t > 0) {
                int tp = lab[t - 1];
                s += trans2[tp * LB + tg];
            }
        }
#pragma unroll
        for (int o = 16; o; o >>= 1) s += __shfl_xor_sync(FULL, s, o);
        float ln = crf_lognorm<LB>(lg2s, trans2, sl);
        if (lane == 0) g_ll2[b] = s - ln;
    } else {
        crf_decode_warp<LB>(lg2s, trans2, sl, bp2, vit2s);
    }
    __syncthreads();

    // fuse: viterbi = where(vit1==0, 0, vit2); accuracy partials
    float c1 = 0.0f, c2 = 0.0f, cc = 0.0f;
    for (int t = threadIdx.x; t < T; t += 128) {
        int v1 = vit1s[t];
        int v2 = vit2s[t];
        int lb = lab[t];
        int vv = (v1 == 0) ? 0 : v2;
        out[b * T + t] = (float)vv;
        if (t < sl) {
            c1 += (v1 == ((lb > 0) ? 1 : 0)) ? 1.0f : 0.0f;
            c2 += (v2 == lb) ? 1.0f : 0.0f;
            cc += (vv == lb) ? 1.0f : 0.0f;
        }
    }
#pragma unroll
    for (int o = 16; o; o >>= 1) {
        c1 += __shfl_xor_sync(FULL, c1, o);
        c2 += __shfl_xor_sync(FULL, c2, o);
        cc += __shfl_xor_sync(FULL, cc, o);
    }
    if (lane == 0) {
        sred[wid] = c1;
        sred[4 + wid] = c2;
        sred[8 + wid] = cc;
    }
    __syncthreads();
    if (threadIdx.x == 0) {
        g_c1[b] = sred[0] + sred[1] + sred[2] + sred[3];
        g_c2[b] = sred[4] + sred[5] + sred[6] + sred[7];
        g_cc[b] = sred[8] + sred[9] + sred[10] + sred[11];
    }
}

// ---------------- final: reduce over B, write scalars --------------------
__global__ void final_kernel(const int* __restrict__ seqlen,
                             float* __restrict__ out, int out_size) {
    int i = threadIdx.x;  // 64 threads
    float vals[6];
    vals[0] = -g_ll1[i];
    vals[1] = -g_ll2[i];
    vals[2] = g_c1[i];
    vals[3] = g_c2[i];
    vals[4] = g_cc[i];
    vals[5] = (float)seqlen[i];
#pragma unroll
    for (int k = 0; k < 6; k++) {
#pragma unroll
        for (int o = 16; o; o >>= 1) vals[k] += __shfl_xor_sync(FULL, vals[k], o);
    }
    __shared__ float sh[2][6];
    if ((i & 31) == 0)
#pragma unroll
        for (int k = 0; k < 6; k++) sh[i >> 5][k] = vals[k];
    __syncthreads();
    if (i == 0) {
        float S[6];
#pragma unroll
        for (int k = 0; k < 6; k++) S[k] = sh[0][k] + sh[1][k];
        float loss1 = S[0] / (float)B;
        float loss2 = S[1] / (float)B;
        float loss = (loss1 + 8.0f * loss2) / 9.0f;
        float tot = S[5];
        int base = out_size - 4;
        out[base + 0] = loss;
        out[base + 1] = S[2] / tot;  // acc1
        out[base + 2] = S[3] / tot;  // acc2
        out[base + 3] = S[4] / tot;  // acc
    }
}

// ---------------- launch -------------------------------------------------
extern "C" void kernel_launch(void* const* d_in, const int* in_sizes, int n_in,
                              void* d_out, int out_size) {
    const float* x      = (const float*)d_in[0];
    const int*   label  = (const int*)d_in[1];
    const int*   seqlen = (const int*)d_in[2];
    const float* W1     = (const float*)d_in[3];
    const float* b1     = (const float*)d_in[4];
    const float* W2     = (const float*)d_in[5];
    const float* b2     = (const float*)d_in[6];
    const float* trans1 = (const float*)d_in[7];
    const float* trans2 = (const float*)d_in[8];
    float* out = (float*)d_out;

    prep_kernel<<<3, 256>>>(W1, W2);
    gemm_kernel<<<(B * T) / 32, 256>>>(x, b1, b2);   // 1024 blocks, 4 rows/warp
    scan_kernel<<<B, 128>>>(label, seqlen, trans1, trans2, out, out_size);
    final_kernel<<<1, 64>>>(seqlen, out, out_size);
}